// round 10
// baseline (speedup 1.0000x reference)
#include <cuda_runtime.h>
#include <stdint.h>

#define NPIX  200704        // 64 * 56 * 56
#define HW    3136          // 56 * 56
#define WID   56
#define NTHR4 (NPIX / 4)    // kB pixel threads: 50176, 4 px each

// Intermediate: 32 sign bits (channels of h) per pixel, layout [b*HW + s]
__device__ uint32_t g_a[NPIX];

// ---------------------------------------------------------------------------
// Kernel A: x [N=64, C=64, 56, 56] (NCHW) -> g_a sign masks.
// 1 px/thread, 784 blocks. Independent accumulator chains for ILP.
// ---------------------------------------------------------------------------
__global__ __launch_bounds__(256) void kA(const float* __restrict__ x,
                                          const float* __restrict__ w1,
                                          const float* __restrict__ g1,
                                          const float* __restrict__ b1,
                                          const float* __restrict__ m1,
                                          const float* __restrict__ v1)
{
    __shared__ unsigned long long sw1[32];
    __shared__ float sinv[32], ssh[32];

    const int wid8 = threadIdx.x >> 5;
    const int lane = threadIdx.x & 31;

#pragma unroll
    for (int o = wid8; o < 32; o += 8) {
        float lo = w1[o * 64 + lane];
        float hi = w1[o * 64 + 32 + lane];
        uint32_t blo = __ballot_sync(0xffffffffu, lo > 0.0f);
        uint32_t bhi = __ballot_sync(0xffffffffu, hi > 0.0f);
        if (lane == 0)
            sw1[o] = (unsigned long long)blo | ((unsigned long long)bhi << 32);
    }
    if (threadIdx.x < 32) {
        int o = threadIdx.x;
        float inv = g1[o] * rsqrtf(v1[o] + 1e-5f);
        sinv[o] = inv;
        ssh[o]  = b1[o] - m1[o] * inv;
    }
    __syncthreads();

    int p = blockIdx.x * 256 + threadIdx.x;   // global pixel index = b*HW + s
    if (p >= NPIX) return;
    int b = p / HW;
    int s = p - b * HW;
    const float* xb = x + (size_t)b * 64 * HW + s;

    // 4 independent 16-bit accumulator chains (ILP), merged at the end.
    uint32_t m0 = 0, m1_ = 0, m2 = 0, m3 = 0;
#pragma unroll
    for (int c = 0; c < 16; c++) {
        if (__ldg(xb + (size_t)c * HW) > 0.0f)        m0  |= 1u << c;
        if (__ldg(xb + (size_t)(c + 16) * HW) > 0.0f) m1_ |= 1u << c;
        if (__ldg(xb + (size_t)(c + 32) * HW) > 0.0f) m2  |= 1u << c;
        if (__ldg(xb + (size_t)(c + 48) * HW) > 0.0f) m3  |= 1u << c;
    }
    unsigned long long xbits =
        (unsigned long long)(m0 | (m1_ << 16)) |
        ((unsigned long long)(m2 | (m3 << 16)) << 32);

    // 2 independent output-bit chains.
    uint32_t alo = 0, ahi = 0;
#pragma unroll
    for (int o = 0; o < 16; o++) {
        {
            int d = 64 - 2 * __popcll(xbits ^ sw1[o]);
            if (fmaf((float)d, sinv[o], ssh[o]) > 0.0f) alo |= 1u << o;
        }
        {
            int o2 = o + 16;
            int d = 64 - 2 * __popcll(xbits ^ sw1[o2]);
            if (fmaf((float)d, sinv[o2], ssh[o2]) > 0.0f) ahi |= 1u << o;
        }
    }
    g_a[p] = alo | (ahi << 16);
}

// ---------------------------------------------------------------------------
// Kernel B: g_a -> output [64,256,56,56].
// Grid (196, 16): blockIdx.x = pixel tile (256 threads x 4 px),
// blockIdx.y = 16-channel group: 0-5 = branch V (w2), 6-11 = branch H (w3),
// 12-15 = branch P (w4). Per-block ballot prep of just its 16 channels.
// smem per channel: uint4{w0,w1,w2,inv_bits} (+ ssh; P packs sh in slot 2).
// ---------------------------------------------------------------------------
__global__ __launch_bounds__(256) void kB(
    const float* __restrict__ w2, const float* __restrict__ g2,
    const float* __restrict__ b2, const float* __restrict__ m2,
    const float* __restrict__ v2,
    const float* __restrict__ w3, const float* __restrict__ g3,
    const float* __restrict__ b3, const float* __restrict__ m3,
    const float* __restrict__ v3,
    const float* __restrict__ w4, const float* __restrict__ g4,
    const float* __restrict__ b4, const float* __restrict__ m4,
    const float* __restrict__ v4,
    float* __restrict__ out)
{
    __shared__ __align__(16) uint32_t sw[16 * 4];
    __shared__ float ssh[16];

    const int grp  = blockIdx.y;        // 0..15
    const int wrp  = threadIdx.x >> 5;  // 0..7
    const int lane = threadIdx.x & 31;

    // ---- per-block prep: 16 channels only
    if (grp < 12) {
        const float* wsrc = (grp < 6) ? w2 : w3;
        const int base = (grp < 6 ? grp : grp - 6) * 16;
#pragma unroll
        for (int o = wrp; o < 16; o += 8) {
            const float* pw = wsrc + ((base + o) * 32 + lane) * 3;
            float a0 = pw[0], a1 = pw[1], a2 = pw[2];
            uint32_t x0 = __ballot_sync(0xffffffffu, a0 > 0.0f);
            uint32_t x1 = __ballot_sync(0xffffffffu, a1 > 0.0f);
            uint32_t x2 = __ballot_sync(0xffffffffu, a2 > 0.0f);
            if (lane == 0) {
                sw[4 * o] = x0; sw[4 * o + 1] = x1; sw[4 * o + 2] = x2;
            }
        }
        if (threadIdx.x < 16) {
            int c = base + threadIdx.x;
            float inv, sh;
            if (grp < 6) {
                inv = g2[c] * rsqrtf(v2[c] + 1e-5f);
                sh  = b2[c] - m2[c] * inv;
            } else {
                inv = g3[c] * rsqrtf(v3[c] + 1e-5f);
                sh  = b3[c] - m3[c] * inv;
            }
            sw[4 * threadIdx.x + 3] = __float_as_uint(inv);
            ssh[threadIdx.x] = sh;
        }
    } else {
        const int base = (grp - 12) * 16;
#pragma unroll
        for (int o = wrp; o < 16; o += 8) {
            uint32_t p = __ballot_sync(0xffffffffu, w4[(base + o) * 32 + lane] > 0.0f);
            if (lane == 0) sw[4 * o] = p;
        }
        if (threadIdx.x < 16) {
            int c = base + threadIdx.x;
            float inv = g4[c] * rsqrtf(v4[c] + 1e-5f);
            sw[4 * threadIdx.x + 1] = __float_as_uint(inv);
            sw[4 * threadIdx.x + 2] = __float_as_uint(b4[c] - m4[c] * inv);
        }
    }
    __syncthreads();

    // ---- pixel group: 4 consecutive pixels along a row
    const int q  = blockIdx.x * 256 + threadIdx.x;  // 0..50175
    const int p  = q * 4;
    const int bb = p / HW;
    const int s  = p - bb * HW;          // multiple of 4
    const int y  = s / WID;
    const int xs = s - y * WID;          // 0..52, multiple of 4

    uint4 C = *(const uint4*)&g_a[p];
    int pc0 = __popc(C.x), pc1 = __popc(C.y), pc2 = __popc(C.z), pc3 = __popc(C.w);

    float* ob = out + (size_t)bb * 256 * HW + s;

    if (grp < 6) {
        // ---- Branch V: 3x1 vertical conv
        uint4 U = make_uint4(0, 0, 0, 0), D = make_uint4(0, 0, 0, 0);
        if (y > 0)  U = *(const uint4*)&g_a[p - WID];
        if (y < 55) D = *(const uint4*)&g_a[p + WID];
        int pv0 = __popc(U.x) + pc0 + __popc(D.x);
        int pv1 = __popc(U.y) + pc1 + __popc(D.y);
        int pv2 = __popc(U.z) + pc2 + __popc(D.z);
        int pv3 = __popc(U.w) + pc3 + __popc(D.w);

        float* o1 = ob + (size_t)(grp * 16) * HW;
#pragma unroll 8
        for (int o = 0; o < 16; o++) {
            uint4 wv = *(const uint4*)&sw[4 * o];
            float inv = __uint_as_float(wv.w);
            float sh  = ssh[o];
            float4 rv;
            int d;
            d = 2 * (__popc(U.x & wv.x) + __popc(C.x & wv.y) + __popc(D.x & wv.z)) - pv0;
            rv.x = fmaxf(fmaf((float)d, inv, sh), 0.0f);
            d = 2 * (__popc(U.y & wv.x) + __popc(C.y & wv.y) + __popc(D.y & wv.z)) - pv1;
            rv.y = fmaxf(fmaf((float)d, inv, sh), 0.0f);
            d = 2 * (__popc(U.z & wv.x) + __popc(C.z & wv.y) + __popc(D.z & wv.z)) - pv2;
            rv.z = fmaxf(fmaf((float)d, inv, sh), 0.0f);
            d = 2 * (__popc(U.w & wv.x) + __popc(C.w & wv.y) + __popc(D.w & wv.z)) - pv3;
            rv.w = fmaxf(fmaf((float)d, inv, sh), 0.0f);
            *(float4*)(o1 + (size_t)o * HW) = rv;
        }
    } else if (grp < 12) {
        // ---- Branch H: 1x3 horizontal conv
        uint32_t hL = (xs > 0)  ? g_a[p - 1] : 0u;
        uint32_t hR = (xs < 52) ? g_a[p + 4] : 0u;
        int pL = __popc(hL), pR = __popc(hR);
        int ph0 = pL  + pc0 + pc1;
        int ph1 = pc0 + pc1 + pc2;
        int ph2 = pc1 + pc2 + pc3;
        int ph3 = pc2 + pc3 + pR;

        float* o2 = ob + (size_t)(96 + (grp - 6) * 16) * HW;
#pragma unroll 8
        for (int o = 0; o < 16; o++) {
            uint4 wv = *(const uint4*)&sw[4 * o];
            float inv = __uint_as_float(wv.w);
            float sh  = ssh[o];
            float4 rv;
            int d;
            d = 2 * (__popc(hL  & wv.x) + __popc(C.x & wv.y) + __popc(C.y & wv.z)) - ph0;
            rv.x = fmaxf(fmaf((float)d, inv, sh), 0.0f);
            d = 2 * (__popc(C.x & wv.x) + __popc(C.y & wv.y) + __popc(C.z & wv.z)) - ph1;
            rv.y = fmaxf(fmaf((float)d, inv, sh), 0.0f);
            d = 2 * (__popc(C.y & wv.x) + __popc(C.z & wv.y) + __popc(C.w & wv.z)) - ph2;
            rv.z = fmaxf(fmaf((float)d, inv, sh), 0.0f);
            d = 2 * (__popc(C.z & wv.x) + __popc(C.w & wv.y) + __popc(hR  & wv.z)) - ph3;
            rv.w = fmaxf(fmaf((float)d, inv, sh), 0.0f);
            *(float4*)(o2 + (size_t)o * HW) = rv;
        }
    } else {
        // ---- Branch P: 1x1 conv (inv in wv.y, sh in wv.z)
        float* o3 = ob + (size_t)(192 + (grp - 12) * 16) * HW;
#pragma unroll 8
        for (int o = 0; o < 16; o++) {
            uint4 wv = *(const uint4*)&sw[4 * o];
            float inv = __uint_as_float(wv.y);
            float sh  = __uint_as_float(wv.z);
            float4 rv;
            rv.x = fmaxf(fmaf((float)(2 * __popc(C.x & wv.x) - pc0), inv, sh), 0.0f);
            rv.y = fmaxf(fmaf((float)(2 * __popc(C.y & wv.x) - pc1), inv, sh), 0.0f);
            rv.z = fmaxf(fmaf((float)(2 * __popc(C.z & wv.x) - pc2), inv, sh), 0.0f);
            rv.w = fmaxf(fmaf((float)(2 * __popc(C.w & wv.x) - pc3), inv, sh), 0.0f);
            *(float4*)(o3 + (size_t)o * HW) = rv;
        }
    }
}

// ---------------------------------------------------------------------------
extern "C" void kernel_launch(void* const* d_in, const int* in_sizes, int n_in,
                              void* d_out, int out_size)
{
    const float* x = (const float*)d_in[0];
    kA<<<NPIX / 256, 256>>>(x,
                            (const float*)d_in[1], (const float*)d_in[2],
                            (const float*)d_in[3], (const float*)d_in[4],
                            (const float*)d_in[5]);
    dim3 gridB(NTHR4 / 256, 16);
    kB<<<gridB, 256>>>(
        (const float*)d_in[6],  (const float*)d_in[7],
        (const float*)d_in[8],  (const float*)d_in[9],
        (const float*)d_in[10],
        (const float*)d_in[11], (const float*)d_in[12],
        (const float*)d_in[13], (const float*)d_in[14],
        (const float*)d_in[15],
        (const float*)d_in[16], (const float*)d_in[17],
        (const float*)d_in[18], (const float*)d_in[19],
        (const float*)d_in[20],
        (float*)d_out);
}

// round 12
// speedup vs baseline: 1.0357x; 1.0357x over previous
#include <cuda_runtime.h>
#include <stdint.h>

#define NPIX  200704        // 64 * 56 * 56
#define HW    3136          // 56 * 56
#define WID   56
#define NTHR4 (NPIX / 4)    // kB pixel threads: 50176, 4 px each

// Intermediate: 32 sign bits (channels of h) per pixel, layout [b*HW + s]
__device__ uint32_t g_a[NPIX];

// ---------------------------------------------------------------------------
// Kernel A: x [N=64, C=64, 56, 56] (NCHW) -> g_a sign masks.
// 1 px/thread, 784 blocks. Independent accumulator chains; streaming loads.
// ---------------------------------------------------------------------------
__global__ __launch_bounds__(256) void kA(const float* __restrict__ x,
                                          const float* __restrict__ w1,
                                          const float* __restrict__ g1,
                                          const float* __restrict__ b1,
                                          const float* __restrict__ m1,
                                          const float* __restrict__ v1)
{
    __shared__ unsigned long long sw1[32];
    __shared__ float sinv[32], ssh[32];

    const int wid8 = threadIdx.x >> 5;
    const int lane = threadIdx.x & 31;

#pragma unroll
    for (int o = wid8; o < 32; o += 8) {
        float lo = w1[o * 64 + lane];
        float hi = w1[o * 64 + 32 + lane];
        uint32_t blo = __ballot_sync(0xffffffffu, lo > 0.0f);
        uint32_t bhi = __ballot_sync(0xffffffffu, hi > 0.0f);
        if (lane == 0)
            sw1[o] = (unsigned long long)blo | ((unsigned long long)bhi << 32);
    }
    if (threadIdx.x < 32) {
        int o = threadIdx.x;
        float inv = g1[o] * rsqrtf(v1[o] + 1e-5f);
        sinv[o] = inv;
        ssh[o]  = b1[o] - m1[o] * inv;
    }
    __syncthreads();

    int p = blockIdx.x * 256 + threadIdx.x;   // global pixel index = b*HW + s
    if (p >= NPIX) return;
    int b = p / HW;
    int s = p - b * HW;
    const float* xb = x + (size_t)b * 64 * HW + s;

    // 4 independent 16-bit accumulator chains (ILP), merged at the end.
    uint32_t m0 = 0, m1_ = 0, m2 = 0, m3 = 0;
#pragma unroll
    for (int c = 0; c < 16; c++) {
        if (__ldcs(xb + (size_t)c * HW) > 0.0f)        m0  |= 1u << c;
        if (__ldcs(xb + (size_t)(c + 16) * HW) > 0.0f) m1_ |= 1u << c;
        if (__ldcs(xb + (size_t)(c + 32) * HW) > 0.0f) m2  |= 1u << c;
        if (__ldcs(xb + (size_t)(c + 48) * HW) > 0.0f) m3  |= 1u << c;
    }
    unsigned long long xbits =
        (unsigned long long)(m0 | (m1_ << 16)) |
        ((unsigned long long)(m2 | (m3 << 16)) << 32);

    // 2 independent output-bit chains.
    uint32_t alo = 0, ahi = 0;
#pragma unroll
    for (int o = 0; o < 16; o++) {
        {
            int d = 64 - 2 * __popcll(xbits ^ sw1[o]);
            if (fmaf((float)d, sinv[o], ssh[o]) > 0.0f) alo |= 1u << o;
        }
        {
            int o2 = o + 16;
            int d = 64 - 2 * __popcll(xbits ^ sw1[o2]);
            if (fmaf((float)d, sinv[o2], ssh[o2]) > 0.0f) ahi |= 1u << o;
        }
    }
    g_a[p] = alo | (ahi << 16);
}

// ---------------------------------------------------------------------------
// Kernel B: g_a -> output [64,256,56,56].
// Grid (196, 8): blockIdx.x = pixel tile (256 threads x 4 px),
// blockIdx.y = 32-channel group: 0-2 = branch V (w2), 3-5 = branch H (w3),
// 6-7 = branch P (w4). g_a loads hoisted above prep; streaming stores.
// ---------------------------------------------------------------------------
__global__ __launch_bounds__(256) void kB(
    const float* __restrict__ w2, const float* __restrict__ g2,
    const float* __restrict__ b2, const float* __restrict__ m2,
    const float* __restrict__ v2,
    const float* __restrict__ w3, const float* __restrict__ g3,
    const float* __restrict__ b3, const float* __restrict__ m3,
    const float* __restrict__ v3,
    const float* __restrict__ w4, const float* __restrict__ g4,
    const float* __restrict__ b4, const float* __restrict__ m4,
    const float* __restrict__ v4,
    float* __restrict__ out)
{
    __shared__ __align__(16) uint32_t sw[32 * 4];
    __shared__ float ssh[32];

    const int grp  = blockIdx.y;        // 0..7
    const int wrp  = threadIdx.x >> 5;  // 0..7
    const int lane = threadIdx.x & 31;

    // ---- pixel indices + hoisted g_a loads (independent of prep)
    const int q  = blockIdx.x * 256 + threadIdx.x;  // 0..50175
    const int p  = q * 4;
    const int bb = p / HW;
    const int s  = p - bb * HW;          // multiple of 4
    const int y  = s / WID;
    const int xs = s - y * WID;          // 0..52, multiple of 4

    uint4 C = *(const uint4*)&g_a[p];
    uint4 U = make_uint4(0, 0, 0, 0), D = make_uint4(0, 0, 0, 0);
    uint32_t hL = 0u, hR = 0u;
    if (grp < 3) {
        if (y > 0)  U = *(const uint4*)&g_a[p - WID];
        if (y < 55) D = *(const uint4*)&g_a[p + WID];
    } else if (grp < 6) {
        hL = (xs > 0)  ? g_a[p - 1] : 0u;
        hR = (xs < 52) ? g_a[p + 4] : 0u;
    }

    // ---- per-block prep: 32 channels only (overlaps the loads above)
    if (grp < 6) {
        const float* wsrc = (grp < 3) ? w2 : w3;
        const int base = (grp < 3 ? grp : grp - 3) * 32;
#pragma unroll
        for (int o = wrp; o < 32; o += 8) {
            const float* pw = wsrc + ((base + o) * 32 + lane) * 3;
            float a0 = pw[0], a1 = pw[1], a2 = pw[2];
            uint32_t x0 = __ballot_sync(0xffffffffu, a0 > 0.0f);
            uint32_t x1 = __ballot_sync(0xffffffffu, a1 > 0.0f);
            uint32_t x2 = __ballot_sync(0xffffffffu, a2 > 0.0f);
            if (lane == 0) {
                sw[4 * o] = x0; sw[4 * o + 1] = x1; sw[4 * o + 2] = x2;
            }
        }
        if (threadIdx.x < 32) {
            int c = base + threadIdx.x;
            float inv, sh;
            if (grp < 3) {
                inv = g2[c] * rsqrtf(v2[c] + 1e-5f);
                sh  = b2[c] - m2[c] * inv;
            } else {
                inv = g3[c] * rsqrtf(v3[c] + 1e-5f);
                sh  = b3[c] - m3[c] * inv;
            }
            sw[4 * threadIdx.x + 3] = __float_as_uint(inv);
            ssh[threadIdx.x] = sh;
        }
    } else {
        const int base = (grp - 6) * 32;
#pragma unroll
        for (int o = wrp; o < 32; o += 8) {
            uint32_t pb = __ballot_sync(0xffffffffu, w4[(base + o) * 32 + lane] > 0.0f);
            if (lane == 0) sw[4 * o] = pb;
        }
        if (threadIdx.x < 32) {
            int c = base + threadIdx.x;
            float inv = g4[c] * rsqrtf(v4[c] + 1e-5f);
            sw[4 * threadIdx.x + 1] = __float_as_uint(inv);
            sw[4 * threadIdx.x + 2] = __float_as_uint(b4[c] - m4[c] * inv);
        }
    }
    __syncthreads();

    int pc0 = __popc(C.x), pc1 = __popc(C.y), pc2 = __popc(C.z), pc3 = __popc(C.w);
    float* ob = out + (size_t)bb * 256 * HW + s;

    if (grp < 3) {
        // ---- Branch V: 3x1 vertical conv
        int pv0 = __popc(U.x) + pc0 + __popc(D.x);
        int pv1 = __popc(U.y) + pc1 + __popc(D.y);
        int pv2 = __popc(U.z) + pc2 + __popc(D.z);
        int pv3 = __popc(U.w) + pc3 + __popc(D.w);

        float* o1 = ob + (size_t)(grp * 32) * HW;
#pragma unroll 8
        for (int o = 0; o < 32; o++) {
            uint4 wv = *(const uint4*)&sw[4 * o];
            float inv = __uint_as_float(wv.w);
            float sh  = ssh[o];
            float4 rv;
            int d;
            d = 2 * (__popc(U.x & wv.x) + __popc(C.x & wv.y) + __popc(D.x & wv.z)) - pv0;
            rv.x = fmaxf(fmaf((float)d, inv, sh), 0.0f);
            d = 2 * (__popc(U.y & wv.x) + __popc(C.y & wv.y) + __popc(D.y & wv.z)) - pv1;
            rv.y = fmaxf(fmaf((float)d, inv, sh), 0.0f);
            d = 2 * (__popc(U.z & wv.x) + __popc(C.z & wv.y) + __popc(D.z & wv.z)) - pv2;
            rv.z = fmaxf(fmaf((float)d, inv, sh), 0.0f);
            d = 2 * (__popc(U.w & wv.x) + __popc(C.w & wv.y) + __popc(D.w & wv.z)) - pv3;
            rv.w = fmaxf(fmaf((float)d, inv, sh), 0.0f);
            __stcs((float4*)(o1 + (size_t)o * HW), rv);
        }
    } else if (grp < 6) {
        // ---- Branch H: 1x3 horizontal conv
        int pL = __popc(hL), pR = __popc(hR);
        int ph0 = pL  + pc0 + pc1;
        int ph1 = pc0 + pc1 + pc2;
        int ph2 = pc1 + pc2 + pc3;
        int ph3 = pc2 + pc3 + pR;

        float* o2 = ob + (size_t)(96 + (grp - 3) * 32) * HW;
#pragma unroll 8
        for (int o = 0; o < 32; o++) {
            uint4 wv = *(const uint4*)&sw[4 * o];
            float inv = __uint_as_float(wv.w);
            float sh  = ssh[o];
            float4 rv;
            int d;
            d = 2 * (__popc(hL  & wv.x) + __popc(C.x & wv.y) + __popc(C.y & wv.z)) - ph0;
            rv.x = fmaxf(fmaf((float)d, inv, sh), 0.0f);
            d = 2 * (__popc(C.x & wv.x) + __popc(C.y & wv.y) + __popc(C.z & wv.z)) - ph1;
            rv.y = fmaxf(fmaf((float)d, inv, sh), 0.0f);
            d = 2 * (__popc(C.y & wv.x) + __popc(C.z & wv.y) + __popc(C.w & wv.z)) - ph2;
            rv.z = fmaxf(fmaf((float)d, inv, sh), 0.0f);
            d = 2 * (__popc(C.z & wv.x) + __popc(C.w & wv.y) + __popc(hR  & wv.z)) - ph3;
            rv.w = fmaxf(fmaf((float)d, inv, sh), 0.0f);
            __stcs((float4*)(o2 + (size_t)o * HW), rv);
        }
    } else {
        // ---- Branch P: 1x1 conv (inv in wv.y, sh in wv.z)
        float* o3 = ob + (size_t)(192 + (grp - 6) * 32) * HW;
#pragma unroll 8
        for (int o = 0; o < 32; o++) {
            uint4 wv = *(const uint4*)&sw[4 * o];
            float inv = __uint_as_float(wv.y);
            float sh  = __uint_as_float(wv.z);
            float4 rv;
            rv.x = fmaxf(fmaf((float)(2 * __popc(C.x & wv.x) - pc0), inv, sh), 0.0f);
            rv.y = fmaxf(fmaf((float)(2 * __popc(C.y & wv.x) - pc1), inv, sh), 0.0f);
            rv.z = fmaxf(fmaf((float)(2 * __popc(C.z & wv.x) - pc2), inv, sh), 0.0f);
            rv.w = fmaxf(fmaf((float)(2 * __popc(C.w & wv.x) - pc3), inv, sh), 0.0f);
            __stcs((float4*)(o3 + (size_t)o * HW), rv);
        }
    }
}

// ---------------------------------------------------------------------------
extern "C" void kernel_launch(void* const* d_in, const int* in_sizes, int n_in,
                              void* d_out, int out_size)
{
    const float* x = (const float*)d_in[0];
    kA<<<NPIX / 256, 256>>>(x,
                            (const float*)d_in[1], (const float*)d_in[2],
                            (const float*)d_in[3], (const float*)d_in[4],
                            (const float*)d_in[5]);
    dim3 gridB(NTHR4 / 256, 8);
    kB<<<gridB, 256>>>(
        (const float*)d_in[6],  (const float*)d_in[7],
        (const float*)d_in[8],  (const float*)d_in[9],
        (const float*)d_in[10],
        (const float*)d_in[11], (const float*)d_in[12],
        (const float*)d_in[13], (const float*)d_in[14],
        (const float*)d_in[15],
        (const float*)d_in[16], (const float*)d_in[17],
        (const float*)d_in[18], (const float*)d_in[19],
        (const float*)d_in[20],
        (float*)d_out);
}